// round 3
// baseline (speedup 1.0000x reference)
#include <cuda_runtime.h>
#include <cuda_bf16.h>
#include <cstdint>

#define N_NODES 100000
#define N_EDGES 3200000

// ---------------- device scratch (static, no allocation) ----------------
__device__ int2  g_edata[N_EDGES];        // per-edge (src, weight-bits) in CSR order
__device__ int   g_rowoff[N_NODES + 1];   // CSR row offsets
__device__ int   g_cursor[N_NODES];       // counts -> scatter cursors
__device__ float g_bufA[N_NODES * 16];    // node feature ping buffer
__device__ float g_bufB[N_NODES * 16];    // node feature pong buffer
__device__ int   g_is32;                  // 1 if edge_index is int32, 0 if int64

// ---------------- CSR build ----------------
__global__ void k_zero() {
    int i = blockIdx.x * 256 + threadIdx.x;
    if (i < N_NODES) g_cursor[i] = 0;
    if (i == 0) g_is32 = 0;
}

// edge_index may be int32 or int64 (little-endian). If int64, every value is a
// node id < 2^31, so all high words are zero. Check 4096 candidate high words.
__global__ void k_detect(const int* __restrict__ ei) {
    int nz = 0;
    for (int i = threadIdx.x; i < 4096; i += 256) nz |= ei[2 * i + 1];
    if (nz) atomicOr(&g_is32, 1);
}

__global__ void k_count(const int* __restrict__ ei) {
    int e = blockIdx.x * 256 + threadIdx.x;
    int dst = g_is32 ? ei[N_EDGES + e] : ei[2 * (N_EDGES + e)];
    atomicAdd(&g_cursor[dst], 1);
}

// single-block exclusive scan of 100k counts (chunk-per-thread + Hillis-Steele)
__global__ void k_scan() {
    __shared__ int s[1024];
    const int t = threadIdx.x;
    const int CH = 98;                      // 1024*98 = 100352 >= N_NODES
    int base = t * CH;
    int end  = min(base + CH, N_NODES);
    int sum = 0;
    for (int i = base; i < end; i++) sum += g_cursor[i];
    s[t] = sum;
    __syncthreads();
    for (int off = 1; off < 1024; off <<= 1) {
        int v = (t >= off) ? s[t - off] : 0;
        __syncthreads();
        s[t] += v;
        __syncthreads();
    }
    int run = s[t] - sum;                   // exclusive prefix
    for (int i = base; i < end; i++) {
        int c = g_cursor[i];
        g_rowoff[i] = run;
        g_cursor[i] = run;                  // scatter cursor
        run += c;
    }
    if (t == 0) g_rowoff[N_NODES] = s[1023];
}

__global__ void k_scatter(const int* __restrict__ ei, const float* __restrict__ ew) {
    int e = blockIdx.x * 256 + threadIdx.x;
    int is32 = g_is32;
    int src = is32 ? ei[e]           : ei[2 * e];
    int dst = is32 ? ei[N_EDGES + e] : ei[2 * (N_EDGES + e)];
    int pos = atomicAdd(&g_cursor[dst], 1);
    g_edata[pos] = make_int2(src, __float_as_int(ew[e]));
}

// ---------------- GEMM1: P1 = x @ W1  (100000 x 512 x 8) ----------------
// 8 warps/block, warp = 4 nodes, lane = (node_local[2b], f[3b]).
// W1 transposed into shared with pad-516 stride (conflict-free float4 reads).
__global__ __launch_bounds__(256) void k_gemm1(const float* __restrict__ x,
                                               const float* __restrict__ W1) {
    __shared__ float sW[8 * 516];
    int tid = threadIdx.x;
    for (int i = tid; i < 4096; i += 256) {
        int k = i >> 3, f = i & 7;
        sW[f * 516 + k] = W1[i];
    }
    __syncthreads();
    int warp = tid >> 5, lane = tid & 31;
    int n = blockIdx.x * 32 + warp * 4 + (lane >> 3);   // grid 3125 -> exactly 100000
    int f = lane & 7;
    const float4* xr = (const float4*)(x + (size_t)n * 512);
    const float4* wr = (const float4*)(sW + f * 516);
    float acc = 0.f;
#pragma unroll 8
    for (int c = 0; c < 128; c++) {
        float4 xv = __ldg(&xr[c]);
        float4 wv = wr[c];
        acc += xv.x * wv.x + xv.y * wv.y + xv.z * wv.z + xv.w * wv.w;
    }
    g_bufA[n * 8 + f] = acc;
}

// ---------------- fused aggregate (+bias+ReLU+next-matmul | +log_softmax) ----
// warp per node. lane = (eg[2b] edge group, fg[3b] feature lane), F2 feats/lane.
template <int FIN, int SIN, int FOUT, int SOUT, bool FINAL, bool INA>
__global__ __launch_bounds__(256) void k_layer(const float* __restrict__ W,
                                               const float* __restrict__ B,
                                               float* __restrict__ outp) {
    constexpr int F2 = FIN / 8;             // 1 or 2
    __shared__ float sW[FINAL ? 1 : FIN * FOUT];
    __shared__ float sB[FINAL ? 10 : FIN];
    int tid = threadIdx.x;
    if (!FINAL) { if (tid < FIN * FOUT) sW[tid] = W[tid]; }
    constexpr int NB = FINAL ? 10 : FIN;
    if (tid < NB) sB[tid] = B[tid];
    __syncthreads();

    const float* Pin = INA ? g_bufA : g_bufB;
    float* Pout = FINAL ? outp : (INA ? g_bufB : g_bufA);

    int warp = tid >> 5, lane = tid & 31;
    int n = blockIdx.x * 8 + warp;          // grid 12500 -> exactly 100000
    int eg = lane >> 3, fg = lane & 7;

    int rs = g_rowoff[n], re = g_rowoff[n + 1];
    float acc0 = 0.f, acc1 = 0.f;
    for (int e = rs + eg; e < re; e += 4) {
        int2 ed = __ldg(&g_edata[e]);
        float w = __int_as_float(ed.y);
        const float* h = Pin + (size_t)ed.x * SIN + fg * F2;
        if (F2 == 1) {
            acc0 += w * __ldg(h);
        } else {
            float2 v = __ldg((const float2*)h);
            acc0 += w * v.x;
            acc1 += w * v.y;
        }
    }
    // reduce across the 4 edge groups (xor 8, xor 16)
    acc0 += __shfl_xor_sync(0xFFFFFFFFu, acc0, 8);
    acc0 += __shfl_xor_sync(0xFFFFFFFFu, acc0, 16);
    if (F2 == 2) {
        acc1 += __shfl_xor_sync(0xFFFFFFFFu, acc1, 8);
        acc1 += __shfl_xor_sync(0xFFFFFFFFu, acc1, 16);
    }
    // broadcast full FIN-vector to every lane
    float hv[FIN];
#pragma unroll
    for (int j = 0; j < FIN; j++) {
        float src = (F2 == 2 && (j & 1)) ? acc1 : acc0;
        hv[j] = __shfl_sync(0xFFFFFFFFu, src, (F2 == 2) ? (j >> 1) : j);
    }

    if (FINAL) {
        float z[10];
        float m = -1e30f;
#pragma unroll
        for (int j = 0; j < 10; j++) { z[j] = hv[j] + sB[j]; m = fmaxf(m, z[j]); }
        float s = 0.f;
#pragma unroll
        for (int j = 0; j < 10; j++) s += expf(z[j] - m);
        float l = m + logf(s);
        if (lane < 10) {
            float zl = 0.f;
#pragma unroll
            for (int j = 0; j < 10; j++)
                if (lane == j) zl = z[j];
            Pout[(size_t)n * 10 + lane] = zl - l;
        }
    } else {
#pragma unroll
        for (int j = 0; j < FIN; j++) hv[j] = fmaxf(hv[j] + sB[j], 0.f);
        if (lane < SOUT) {
            float o = 0.f;
            if (lane < FOUT) {
#pragma unroll
                for (int j = 0; j < FIN; j++) o += hv[j] * sW[j * FOUT + lane];
            }
            Pout[(size_t)n * SOUT + lane] = o;   // lanes FOUT..SOUT-1 write pad zeros
        }
    }
}

// ---------------- launch ----------------
extern "C" void kernel_launch(void* const* d_in, const int* in_sizes, int n_in,
                              void* d_out, int out_size) {
    const float* x  = (const float*)d_in[0];
    const int*   ei = (const int*)d_in[1];     // int32 or int64 (detected at runtime)
    const float* ew = (const float*)d_in[2];
    const float* W1 = (const float*)d_in[3];
    const float* b1 = (const float*)d_in[4];
    const float* W2 = (const float*)d_in[5];
    const float* b2 = (const float*)d_in[6];
    const float* W3 = (const float*)d_in[7];
    const float* b3 = (const float*)d_in[8];
    const float* W4 = (const float*)d_in[9];
    const float* b4 = (const float*)d_in[10];
    float* out = (float*)d_out;

    // CSR build (per launch; graph-capturable, deterministic up to fp order)
    k_zero<<<(N_NODES + 255) / 256, 256>>>();
    k_detect<<<1, 256>>>(ei);
    k_count<<<N_EDGES / 256, 256>>>(ei);
    k_scan<<<1, 1024>>>();
    k_scatter<<<N_EDGES / 256, 256>>>(ei, ew);

    // layer pipeline
    k_gemm1<<<N_NODES / 32, 256>>>(x, W1);                         // P1 -> A (stride 8)
    k_layer< 8,  8, 16, 16, false, true ><<<N_NODES / 8, 256>>>(W2, b1, nullptr); // A->B
    k_layer<16, 16,  8,  8, false, false><<<N_NODES / 8, 256>>>(W3, b2, nullptr); // B->A
    k_layer< 8,  8, 10, 16, false, true ><<<N_NODES / 8, 256>>>(W4, b3, nullptr); // A->B (pad 16)
    k_layer<16, 16, 10, 10, true,  false><<<N_NODES / 8, 256>>>(nullptr, b4, out);
}

// round 4
// speedup vs baseline: 1.3990x; 1.3990x over previous
#include <cuda_runtime.h>
#include <cuda_bf16.h>
#include <cstdint>

#define N_NODES 100000
#define N_EDGES 3200000
#define NBLK_SCAN 98            // ceil(100000 / 1024)

// ---------------- device scratch (static, no allocation) ----------------
__device__ int2  g_edata[N_EDGES];        // per-edge (src, weight-bits) in CSR order
__device__ int   g_rowoff[N_NODES + 1];   // CSR row offsets
__device__ int   g_cursor[N_NODES];       // counts -> scatter cursors
__device__ int   g_bsum[128];             // per-block sums for scan (98 used)
__device__ float g_bufA[N_NODES * 16];    // node feature ping buffer
__device__ float g_bufB[N_NODES * 16];    // node feature pong buffer
__device__ int   g_is32;                  // 1 if edge_index is int32, 0 if int64

// ---------------- CSR build ----------------
__global__ void k_zero() {
    int i = blockIdx.x * 256 + threadIdx.x;
    if (i < N_NODES) g_cursor[i] = 0;
    if (i == 0) { g_is32 = 0; g_rowoff[N_NODES] = N_EDGES; }
}

// edge_index may be int32 or int64 (little-endian). If int64, every value is a
// node id < 2^31, so all high words are zero. Check 4096 candidate high words.
__global__ void k_detect(const int* __restrict__ ei) {
    int nz = 0;
    for (int i = threadIdx.x; i < 4096; i += 256) nz |= ei[2 * i + 1];
    if (nz) atomicOr(&g_is32, 1);
}

__global__ void k_count(const int* __restrict__ ei) {
    int e = blockIdx.x * 256 + threadIdx.x;
    int dst = g_is32 ? ei[N_EDGES + e] : ei[2 * (N_EDGES + e)];
    atomicAdd(&g_cursor[dst], 1);
}

__device__ __forceinline__ int warp_incl_scan(int v, int lane) {
#pragma unroll
    for (int o = 1; o < 32; o <<= 1) {
        int u = __shfl_up_sync(0xFFFFFFFFu, v, o);
        if (lane >= o) v += u;
    }
    return v;
}

// pass 1: per-block sums of 1024 counts each
__global__ __launch_bounds__(256) void k_reduce() {
    __shared__ int sw[8];
    int b = blockIdx.x, t = threadIdx.x;
    int base = b * 1024 + t * 4;
    int s = 0;
#pragma unroll
    for (int j = 0; j < 4; j++)
        if (base + j < N_NODES) s += g_cursor[base + j];
    int lane = t & 31, w = t >> 5;
#pragma unroll
    for (int o = 16; o; o >>= 1) s += __shfl_xor_sync(0xFFFFFFFFu, s, o);
    if (lane == 0) sw[w] = s;
    __syncthreads();
    if (t == 0) {
        int tot = 0;
#pragma unroll
        for (int j = 0; j < 8; j++) tot += sw[j];
        g_bsum[b] = tot;
    }
}

// pass 2: exclusive scan of the 98 block sums (single tiny block)
__global__ void k_top() {
    __shared__ int sw[4];
    int t = threadIdx.x;                 // 128 threads
    int v = (t < NBLK_SCAN) ? g_bsum[t] : 0;
    int lane = t & 31, w = t >> 5;
    int incl = warp_incl_scan(v, lane);
    if (lane == 31) sw[w] = incl;
    __syncthreads();
    int bex = 0;
    for (int j = 0; j < w; j++) bex += sw[j];
    if (t < NBLK_SCAN) g_bsum[t] = bex + incl - v;   // exclusive prefix
}

// pass 3: block-local exclusive scan (4 items/thread) + block offset
__global__ __launch_bounds__(256) void k_apply() {
    __shared__ int sw[8];
    int b = blockIdx.x, t = threadIdx.x;
    int base = b * 1024 + t * 4;
    int c0 = (base + 0 < N_NODES) ? g_cursor[base + 0] : 0;
    int c1 = (base + 1 < N_NODES) ? g_cursor[base + 1] : 0;
    int c2 = (base + 2 < N_NODES) ? g_cursor[base + 2] : 0;
    int c3 = (base + 3 < N_NODES) ? g_cursor[base + 3] : 0;
    int l1 = c0 + c1, l2 = l1 + c2, l3 = l2 + c3;
    int lane = t & 31, w = t >> 5;
    int incl = warp_incl_scan(l3, lane);
    int wex = incl - l3;                 // exclusive within warp
    if (lane == 31) sw[w] = incl;
    __syncthreads();
    int bex = 0;
    for (int j = 0; j < w; j++) bex += sw[j];
    int off = g_bsum[b] + bex + wex;
    if (base + 0 < N_NODES) { g_rowoff[base + 0] = off;      g_cursor[base + 0] = off;      }
    if (base + 1 < N_NODES) { g_rowoff[base + 1] = off + c0; g_cursor[base + 1] = off + c0; }
    if (base + 2 < N_NODES) { g_rowoff[base + 2] = off + l1; g_cursor[base + 2] = off + l1; }
    if (base + 3 < N_NODES) { g_rowoff[base + 3] = off + l2; g_cursor[base + 3] = off + l2; }
}

__global__ void k_scatter(const int* __restrict__ ei, const float* __restrict__ ew) {
    int e = blockIdx.x * 256 + threadIdx.x;
    int is32 = g_is32;
    int src = is32 ? ei[e]           : ei[2 * e];
    int dst = is32 ? ei[N_EDGES + e] : ei[2 * (N_EDGES + e)];
    int pos = atomicAdd(&g_cursor[dst], 1);
    g_edata[pos] = make_int2(src, __float_as_int(ew[e]));
}

// ---------------- GEMM1: P1 = x @ W1  (100000 x 512 x 8) ----------------
// 8 warps/block, warp = 4 nodes, lane = (node_local[2b], f[3b]).
// W1 transposed into shared with pad-516 stride (conflict-free float4 reads).
__global__ __launch_bounds__(256) void k_gemm1(const float* __restrict__ x,
                                               const float* __restrict__ W1) {
    __shared__ float sW[8 * 516];
    int tid = threadIdx.x;
    for (int i = tid; i < 4096; i += 256) {
        int k = i >> 3, f = i & 7;
        sW[f * 516 + k] = W1[i];
    }
    __syncthreads();
    int warp = tid >> 5, lane = tid & 31;
    int n = blockIdx.x * 32 + warp * 4 + (lane >> 3);   // grid 3125 -> exactly 100000
    int f = lane & 7;
    const float4* xr = (const float4*)(x + (size_t)n * 512);
    const float4* wr = (const float4*)(sW + f * 516);
    float acc = 0.f;
#pragma unroll 8
    for (int c = 0; c < 128; c++) {
        float4 xv = __ldg(&xr[c]);
        float4 wv = wr[c];
        acc += xv.x * wv.x + xv.y * wv.y + xv.z * wv.z + xv.w * wv.w;
    }
    g_bufA[n * 8 + f] = acc;
}

// ---------------- fused aggregate (+bias+ReLU+next-matmul | +log_softmax) ----
// warp per node. lane = (eg[2b] edge group, fg[3b] feature lane), F2 feats/lane.
template <int FIN, int SIN, int FOUT, int SOUT, bool FINAL, bool INA>
__global__ __launch_bounds__(256) void k_layer(const float* __restrict__ W,
                                               const float* __restrict__ B,
                                               float* __restrict__ outp) {
    constexpr int F2 = FIN / 8;             // 1 or 2
    __shared__ float sW[FINAL ? 1 : FIN * FOUT];
    __shared__ float sB[FINAL ? 10 : FIN];
    int tid = threadIdx.x;
    if (!FINAL) { if (tid < FIN * FOUT) sW[tid] = W[tid]; }
    constexpr int NB = FINAL ? 10 : FIN;
    if (tid < NB) sB[tid] = B[tid];
    __syncthreads();

    const float* Pin = INA ? g_bufA : g_bufB;
    float* Pout = FINAL ? outp : (INA ? g_bufB : g_bufA);

    int warp = tid >> 5, lane = tid & 31;
    int n = blockIdx.x * 8 + warp;          // grid 12500 -> exactly 100000
    int eg = lane >> 3, fg = lane & 7;

    int rs = g_rowoff[n], re = g_rowoff[n + 1];
    float acc0 = 0.f, acc1 = 0.f;
#pragma unroll 4
    for (int e = rs + eg; e < re; e += 4) {
        int2 ed = __ldg(&g_edata[e]);
        float w = __int_as_float(ed.y);
        const float* h = Pin + (size_t)ed.x * SIN + fg * F2;
        if (F2 == 1) {
            acc0 += w * __ldg(h);
        } else {
            float2 v = __ldg((const float2*)h);
            acc0 += w * v.x;
            acc1 += w * v.y;
        }
    }
    // reduce across the 4 edge groups (xor 8, xor 16)
    acc0 += __shfl_xor_sync(0xFFFFFFFFu, acc0, 8);
    acc0 += __shfl_xor_sync(0xFFFFFFFFu, acc0, 16);
    if (F2 == 2) {
        acc1 += __shfl_xor_sync(0xFFFFFFFFu, acc1, 8);
        acc1 += __shfl_xor_sync(0xFFFFFFFFu, acc1, 16);
    }
    // broadcast full FIN-vector to every lane
    float hv[FIN];
#pragma unroll
    for (int j = 0; j < FIN; j++) {
        float src = (F2 == 2 && (j & 1)) ? acc1 : acc0;
        hv[j] = __shfl_sync(0xFFFFFFFFu, src, (F2 == 2) ? (j >> 1) : j);
    }

    if (FINAL) {
        float z[10];
        float m = -1e30f;
#pragma unroll
        for (int j = 0; j < 10; j++) { z[j] = hv[j] + sB[j]; m = fmaxf(m, z[j]); }
        float s = 0.f;
#pragma unroll
        for (int j = 0; j < 10; j++) s += expf(z[j] - m);
        float l = m + logf(s);
        if (lane < 10) {
            float zl = 0.f;
#pragma unroll
            for (int j = 0; j < 10; j++)
                if (lane == j) zl = z[j];
            Pout[(size_t)n * 10 + lane] = zl - l;
        }
    } else {
#pragma unroll
        for (int j = 0; j < FIN; j++) hv[j] = fmaxf(hv[j] + sB[j], 0.f);
        if (lane < SOUT) {
            float o = 0.f;
            if (lane < FOUT) {
#pragma unroll
                for (int j = 0; j < FIN; j++) o += hv[j] * sW[j * FOUT + lane];
            }
            Pout[(size_t)n * SOUT + lane] = o;   // lanes FOUT..SOUT-1 write pad zeros
        }
    }
}

// ---------------- launch ----------------
extern "C" void kernel_launch(void* const* d_in, const int* in_sizes, int n_in,
                              void* d_out, int out_size) {
    const float* x  = (const float*)d_in[0];
    const int*   ei = (const int*)d_in[1];     // int32 or int64 (detected at runtime)
    const float* ew = (const float*)d_in[2];
    const float* W1 = (const float*)d_in[3];
    const float* b1 = (const float*)d_in[4];
    const float* W2 = (const float*)d_in[5];
    const float* b2 = (const float*)d_in[6];
    const float* W3 = (const float*)d_in[7];
    const float* b3 = (const float*)d_in[8];
    const float* W4 = (const float*)d_in[9];
    const float* b4 = (const float*)d_in[10];
    float* out = (float*)d_out;

    // CSR build (per launch; graph-capturable, deterministic up to fp order)
    k_zero<<<(N_NODES + 255) / 256, 256>>>();
    k_detect<<<1, 256>>>(ei);
    k_count<<<N_EDGES / 256, 256>>>(ei);
    k_reduce<<<NBLK_SCAN, 256>>>();
    k_top<<<1, 128>>>();
    k_apply<<<NBLK_SCAN, 256>>>();
    k_scatter<<<N_EDGES / 256, 256>>>(ei, ew);

    // layer pipeline
    k_gemm1<<<N_NODES / 32, 256>>>(x, W1);                         // P1 -> A (stride 8)
    k_layer< 8,  8, 16, 16, false, true ><<<N_NODES / 8, 256>>>(W2, b1, nullptr); // A->B
    k_layer<16, 16,  8,  8, false, false><<<N_NODES / 8, 256>>>(W3, b2, nullptr); // B->A
    k_layer< 8,  8, 10, 16, false, true ><<<N_NODES / 8, 256>>>(W4, b3, nullptr); // A->B (pad 16)
    k_layer<16, 16, 10, 10, true,  false><<<N_NODES / 8, 256>>>(nullptr, b4, out);
}

// round 5
// speedup vs baseline: 1.4473x; 1.0345x over previous
#include <cuda_runtime.h>
#include <cuda_bf16.h>
#include <cstdint>

#define N_NODES 100000
#define N_EDGES 3200000
#define NBLK_SCAN 98            // ceil(100000 / 1024)
#define GEMM_BLKS 3125          // 100000 / 32 nodes
#define CNT_BLKS  3125          // 3.2M / (256*4) edges
#define SCAT_BLKS 6250          // 3.2M / (256*2) edges

// ---------------- device scratch (static, no allocation) ----------------
__device__ int2  g_edata[N_EDGES];        // per-edge (src, weight-bits) in CSR order
__device__ int   g_rowoff[N_NODES + 1];   // CSR row offsets
__device__ int   g_cursor[N_NODES];       // counts -> scatter cursors
__device__ int   g_bsum[128];             // per-block sums for scan (98 used)
__device__ float g_bufA[N_NODES * 16];    // node feature ping buffer
__device__ float g_bufB[N_NODES * 16];    // node feature pong buffer
__device__ int   g_is32;                  // 1 if edge_index is int32, 0 if int64

// ---------------- zero + dtype detect (fused) ----------------
// Block 390 detects dtype (it has no zeroing work beyond 100000); single writer.
__global__ __launch_bounds__(256) void k_zero_detect(const int* __restrict__ ei) {
    int i = blockIdx.x * 256 + threadIdx.x;
    if (i < N_NODES) g_cursor[i] = 0;
    if (i == 0) g_rowoff[N_NODES] = N_EDGES;
    if (blockIdx.x == 390) {
        // int64 edge ids < 2^31 have all-zero high words at odd int32 offsets.
        int nz = 0;
        for (int k = threadIdx.x; k < 4096; k += 256) nz |= ei[2 * k + 1];
        int any = __syncthreads_or(nz);
        if (threadIdx.x == 0) g_is32 = (any != 0);
    }
}

// ---------------- fused GEMM1 + degree count ----------------
// blocks [0, GEMM_BLKS): P1 = x @ W1  (DRAM-bound)
// blocks [GEMM_BLKS, GEMM_BLKS+CNT_BLKS): degree histogram (L2-atomic-bound)
// Roles use disjoint resources -> waves overlap the two bottlenecks.
__global__ __launch_bounds__(256) void k_gemm_count(const float* __restrict__ x,
                                                    const float* __restrict__ W1,
                                                    const int* __restrict__ ei) {
    if (blockIdx.x < GEMM_BLKS) {
        __shared__ float sW[8 * 516];
        int tid = threadIdx.x;
        for (int i = tid; i < 4096; i += 256) {
            int k = i >> 3, f = i & 7;
            sW[f * 516 + k] = W1[i];
        }
        __syncthreads();
        int warp = tid >> 5, lane = tid & 31;
        int n = blockIdx.x * 32 + warp * 4 + (lane >> 3);
        int f = lane & 7;
        const float4* xr = (const float4*)(x + (size_t)n * 512);
        const float4* wr = (const float4*)(sW + f * 516);
        float acc = 0.f;
#pragma unroll 8
        for (int c = 0; c < 128; c++) {
            float4 xv = __ldg(&xr[c]);
            float4 wv = wr[c];
            acc += xv.x * wv.x + xv.y * wv.y + xv.z * wv.z + xv.w * wv.w;
        }
        g_bufA[n * 8 + f] = acc;
    } else {
        // count role: 4 edges per thread, vectorized dst loads
        int t = (blockIdx.x - GEMM_BLKS) * 256 + threadIdx.x;   // 0..800000
        if (g_is32) {
            int4 d = __ldg((const int4*)(ei + N_EDGES + 4 * t));
            atomicAdd(&g_cursor[d.x], 1);
            atomicAdd(&g_cursor[d.y], 1);
            atomicAdd(&g_cursor[d.z], 1);
            atomicAdd(&g_cursor[d.w], 1);
        } else {
            const int4* p = (const int4*)(ei + 2 * N_EDGES + 8 * t);
            int4 a = __ldg(p), b = __ldg(p + 1);
            atomicAdd(&g_cursor[a.x], 1);
            atomicAdd(&g_cursor[a.z], 1);
            atomicAdd(&g_cursor[b.x], 1);
            atomicAdd(&g_cursor[b.z], 1);
        }
    }
}

__device__ __forceinline__ int warp_incl_scan(int v, int lane) {
#pragma unroll
    for (int o = 1; o < 32; o <<= 1) {
        int u = __shfl_up_sync(0xFFFFFFFFu, v, o);
        if (lane >= o) v += u;
    }
    return v;
}

// scan pass 1: per-block sums of 1024 counts each
__global__ __launch_bounds__(256) void k_reduce() {
    __shared__ int sw[8];
    int b = blockIdx.x, t = threadIdx.x;
    int base = b * 1024 + t * 4;
    int s = 0;
#pragma unroll
    for (int j = 0; j < 4; j++)
        if (base + j < N_NODES) s += g_cursor[base + j];
    int lane = t & 31, w = t >> 5;
#pragma unroll
    for (int o = 16; o; o >>= 1) s += __shfl_xor_sync(0xFFFFFFFFu, s, o);
    if (lane == 0) sw[w] = s;
    __syncthreads();
    if (t == 0) {
        int tot = 0;
#pragma unroll
        for (int j = 0; j < 8; j++) tot += sw[j];
        g_bsum[b] = tot;
    }
}

// scan pass 2: exclusive scan of the 98 block sums
__global__ void k_top() {
    __shared__ int sw[4];
    int t = threadIdx.x;                 // 128 threads
    int v = (t < NBLK_SCAN) ? g_bsum[t] : 0;
    int lane = t & 31, w = t >> 5;
    int incl = warp_incl_scan(v, lane);
    if (lane == 31) sw[w] = incl;
    __syncthreads();
    int bex = 0;
    for (int j = 0; j < w; j++) bex += sw[j];
    if (t < NBLK_SCAN) g_bsum[t] = bex + incl - v;
}

// scan pass 3: block-local exclusive scan + block offset
__global__ __launch_bounds__(256) void k_apply() {
    __shared__ int sw[8];
    int b = blockIdx.x, t = threadIdx.x;
    int base = b * 1024 + t * 4;
    int c0 = (base + 0 < N_NODES) ? g_cursor[base + 0] : 0;
    int c1 = (base + 1 < N_NODES) ? g_cursor[base + 1] : 0;
    int c2 = (base + 2 < N_NODES) ? g_cursor[base + 2] : 0;
    int c3 = (base + 3 < N_NODES) ? g_cursor[base + 3] : 0;
    int l1 = c0 + c1, l2 = l1 + c2, l3 = l2 + c3;
    int lane = t & 31, w = t >> 5;
    int incl = warp_incl_scan(l3, lane);
    int wex = incl - l3;
    if (lane == 31) sw[w] = incl;
    __syncthreads();
    int bex = 0;
    for (int j = 0; j < w; j++) bex += sw[j];
    int off = g_bsum[b] + bex + wex;
    if (base + 0 < N_NODES) { g_rowoff[base + 0] = off;      g_cursor[base + 0] = off;      }
    if (base + 1 < N_NODES) { g_rowoff[base + 1] = off + c0; g_cursor[base + 1] = off + c0; }
    if (base + 2 < N_NODES) { g_rowoff[base + 2] = off + l1; g_cursor[base + 2] = off + l1; }
    if (base + 3 < N_NODES) { g_rowoff[base + 3] = off + l2; g_cursor[base + 3] = off + l2; }
}

// scatter: 2 edges per thread, vectorized src/dst/weight loads
__global__ __launch_bounds__(256) void k_scatter(const int* __restrict__ ei,
                                                 const float* __restrict__ ew) {
    int t = blockIdx.x * 256 + threadIdx.x;      // 0..1.6M
    int s0, s1, d0, d1;
    if (g_is32) {
        int2 s = __ldg((const int2*)(ei + 2 * t));
        int2 d = __ldg((const int2*)(ei + N_EDGES + 2 * t));
        s0 = s.x; s1 = s.y; d0 = d.x; d1 = d.y;
    } else {
        int4 s = __ldg((const int4*)(ei + 4 * t));
        int4 d = __ldg((const int4*)(ei + 2 * N_EDGES + 4 * t));
        s0 = s.x; s1 = s.z; d0 = d.x; d1 = d.z;
    }
    float2 w = __ldg((const float2*)(ew + 2 * t));
    int p0 = atomicAdd(&g_cursor[d0], 1);
    g_edata[p0] = make_int2(s0, __float_as_int(w.x));
    int p1 = atomicAdd(&g_cursor[d1], 1);
    g_edata[p1] = make_int2(s1, __float_as_int(w.y));
}

// ---------------- fused aggregate (+bias+ReLU+next-matmul | +log_softmax) ----
// warp per node. lane = (eg[2b] edge group, fg[3b] feature lane), F2 feats/lane.
template <int FIN, int SIN, int FOUT, int SOUT, bool FINAL, bool INA>
__global__ __launch_bounds__(256) void k_layer(const float* __restrict__ W,
                                               const float* __restrict__ B,
                                               float* __restrict__ outp) {
    constexpr int F2 = FIN / 8;             // 1 or 2
    __shared__ float sW[FINAL ? 1 : FIN * FOUT];
    __shared__ float sB[FINAL ? 10 : FIN];
    int tid = threadIdx.x;
    if (!FINAL) { if (tid < FIN * FOUT) sW[tid] = W[tid]; }
    constexpr int NB = FINAL ? 10 : FIN;
    if (tid < NB) sB[tid] = B[tid];
    __syncthreads();

    const float* Pin = INA ? g_bufA : g_bufB;
    float* Pout = FINAL ? outp : (INA ? g_bufB : g_bufA);

    int warp = tid >> 5, lane = tid & 31;
    int n = blockIdx.x * 8 + warp;          // grid 12500 -> exactly 100000
    int eg = lane >> 3, fg = lane & 7;

    int rs = g_rowoff[n], re = g_rowoff[n + 1];
    float acc0 = 0.f, acc1 = 0.f;
#pragma unroll 4
    for (int e = rs + eg; e < re; e += 4) {
        int2 ed = __ldg(&g_edata[e]);
        float w = __int_as_float(ed.y);
        const float* h = Pin + (size_t)ed.x * SIN + fg * F2;
        if (F2 == 1) {
            acc0 += w * __ldg(h);
        } else {
            float2 v = __ldg((const float2*)h);
            acc0 += w * v.x;
            acc1 += w * v.y;
        }
    }
    // reduce across the 4 edge groups
    acc0 += __shfl_xor_sync(0xFFFFFFFFu, acc0, 8);
    acc0 += __shfl_xor_sync(0xFFFFFFFFu, acc0, 16);
    if (F2 == 2) {
        acc1 += __shfl_xor_sync(0xFFFFFFFFu, acc1, 8);
        acc1 += __shfl_xor_sync(0xFFFFFFFFu, acc1, 16);
    }
    // broadcast full FIN-vector to every lane
    float hv[FIN];
#pragma unroll
    for (int j = 0; j < FIN; j++) {
        float src = (F2 == 2 && (j & 1)) ? acc1 : acc0;
        hv[j] = __shfl_sync(0xFFFFFFFFu, src, (F2 == 2) ? (j >> 1) : j);
    }

    if (FINAL) {
        float z[10];
        float m = -1e30f;
#pragma unroll
        for (int j = 0; j < 10; j++) { z[j] = hv[j] + sB[j]; m = fmaxf(m, z[j]); }
        float s = 0.f;
#pragma unroll
        for (int j = 0; j < 10; j++) s += expf(z[j] - m);
        float l = m + logf(s);
        if (lane < 10) {
            float zl = 0.f;
#pragma unroll
            for (int j = 0; j < 10; j++)
                if (lane == j) zl = z[j];
            Pout[(size_t)n * 10 + lane] = zl - l;
        }
    } else {
#pragma unroll
        for (int j = 0; j < FIN; j++) hv[j] = fmaxf(hv[j] + sB[j], 0.f);
        if (lane < SOUT) {
            float o = 0.f;
            if (lane < FOUT) {
#pragma unroll
                for (int j = 0; j < FIN; j++) o += hv[j] * sW[j * FOUT + lane];
            }
            Pout[(size_t)n * SOUT + lane] = o;   // lanes FOUT..SOUT-1 write pad zeros
        }
    }
}

// ---------------- launch ----------------
extern "C" void kernel_launch(void* const* d_in, const int* in_sizes, int n_in,
                              void* d_out, int out_size) {
    const float* x  = (const float*)d_in[0];
    const int*   ei = (const int*)d_in[1];     // int32 or int64 (detected at runtime)
    const float* ew = (const float*)d_in[2];
    const float* W1 = (const float*)d_in[3];
    const float* b1 = (const float*)d_in[4];
    const float* W2 = (const float*)d_in[5];
    const float* b2 = (const float*)d_in[6];
    const float* W3 = (const float*)d_in[7];
    const float* b3 = (const float*)d_in[8];
    const float* W4 = (const float*)d_in[9];
    const float* b4 = (const float*)d_in[10];
    float* out = (float*)d_out;

    // CSR build + GEMM1, overlapped via block-role fusion
    k_zero_detect<<<(N_NODES + 255) / 256, 256>>>(ei);
    k_gemm_count<<<GEMM_BLKS + CNT_BLKS, 256>>>(x, W1, ei);
    k_reduce<<<NBLK_SCAN, 256>>>();
    k_top<<<1, 128>>>();
    k_apply<<<NBLK_SCAN, 256>>>();
    k_scatter<<<SCAT_BLKS, 256>>>(ei, ew);

    // layer pipeline
    k_layer< 8,  8, 16, 16, false, true ><<<N_NODES / 8, 256>>>(W2, b1, nullptr); // A->B
    k_layer<16, 16,  8,  8, false, false><<<N_NODES / 8, 256>>>(W3, b2, nullptr); // B->A
    k_layer< 8,  8, 10, 16, false, true ><<<N_NODES / 8, 256>>>(W4, b3, nullptr); // A->B (pad 16)
    k_layer<16, 16, 10, 10, true,  false><<<N_NODES / 8, 256>>>(nullptr, b4, out);
}